// round 8
// baseline (speedup 1.0000x reference)
#include <cuda_runtime.h>
#include <cuda_bf16.h>
#include <cstdint>

#define N_NODES 50000
#define N_EDGES 600000
#define D_IN    128
#define D_HID   1024
#define D_OUT   128
#define NBLK_SCAN ((N_NODES + 255) / 256)   // 196

// ---------------------------------------------------------------------------
// Device-global scratch. ONLY referenced from device code (host-shadow bug).
// ---------------------------------------------------------------------------
__device__ float         g_h[(size_t)N_NODES * D_IN];         // fp32 aggregate
__device__ __nv_bfloat16 g_w1t_hi[(size_t)D_HID * D_IN];      // W1^T [1024][128]
__device__ __nv_bfloat16 g_w1t_lo[(size_t)D_HID * D_IN];
__device__ __nv_bfloat16 g_w2t_hi[(size_t)D_OUT * D_HID];     // W2^T [128][1024]
__device__ __nv_bfloat16 g_w2t_lo[(size_t)D_OUT * D_HID];
// CSR build
__device__ int g_cnt[N_NODES];
__device__ int g_off[N_NODES];
__device__ int g_cur[N_NODES];
__device__ int g_blksum[NBLK_SCAN];
__device__ int g_eid[N_EDGES];
__device__ int g_esrc[N_EDGES];

// ---------------------------------------------------------------------------
// Helpers
// ---------------------------------------------------------------------------
__device__ __forceinline__ uint32_t smem_u32(const void* p) {
    uint32_t a;
    asm("{ .reg .u64 t; cvta.to.shared.u64 t, %1; cvt.u32.u64 %0, t; }" : "=r"(a) : "l"(p));
    return a;
}
#define SW128(x) ((x) ^ (((x) >> 3) & 0x70))

// 128-row x 128-bf16-k tile: two sequential 16KB sub-tiles, 128B/row SW128.
__device__ __forceinline__ uint32_t toff(int row, int kbyte) {
    uint32_t w = (uint32_t)(row * 128 + (kbyte & 127));
    return (uint32_t)((kbyte >> 7) * 16384) + SW128(w);
}

__device__ __forceinline__ void ldsm_x4(uint32_t (&r)[4], uint32_t addr) {
    asm volatile("ldmatrix.sync.aligned.m8n8.x4.shared.b16 {%0,%1,%2,%3}, [%4];"
                 : "=r"(r[0]), "=r"(r[1]), "=r"(r[2]), "=r"(r[3]) : "r"(addr));
}
__device__ __forceinline__ void mma_bf16(float (&d)[4], const uint32_t (&a)[4],
                                         uint32_t b0, uint32_t b1) {
    asm volatile(
        "mma.sync.aligned.m16n8k16.row.col.f32.bf16.bf16.f32 "
        "{%0,%1,%2,%3}, {%4,%5,%6,%7}, {%8,%9}, {%0,%1,%2,%3};"
        : "+f"(d[0]), "+f"(d[1]), "+f"(d[2]), "+f"(d[3])
        : "r"(a[0]), "r"(a[1]), "r"(a[2]), "r"(a[3]), "r"(b0), "r"(b1));
}
__device__ __forceinline__ uint32_t pack_bf2(float x0, float x1) {
    __nv_bfloat162 p = __floats2bfloat162_rn(x0, x1);
    return *reinterpret_cast<uint32_t*>(&p);
}

// 128x128x128 3-term split MMA (validated mapping from R6/R7).
__device__ __forceinline__ void mma_tile_128(uint32_t a_hi, uint32_t a_lo,
                                             uint32_t b_hi, uint32_t b_lo,
                                             float (&acc)[2][8][4],
                                             int lane, int wm, int wn) {
#pragma unroll
    for (int ks = 0; ks < 8; ks++) {
        const int kb = ks * 32;
        uint32_t ah[2][4], al[2][4];
#pragma unroll
        for (int mt = 0; mt < 2; mt++) {
            int arow = wm * 32 + mt * 16 + (lane & 15);
            uint32_t off = toff(arow, kb + (lane >> 4) * 16);
            ldsm_x4(ah[mt], a_hi + off);
            ldsm_x4(al[mt], a_lo + off);
        }
#pragma unroll
        for (int p = 0; p < 4; p++) {
            int brow = wn * 64 + p * 16 + (lane >> 4) * 8 + (lane & 7);
            uint32_t off = toff(brow, kb + ((lane >> 3) & 1) * 16);
            uint32_t bh[4], bl[4];
            ldsm_x4(bh, b_hi + off);
            ldsm_x4(bl, b_lo + off);
#pragma unroll
            for (int mt = 0; mt < 2; mt++) {
                mma_bf16(acc[mt][2 * p],     ah[mt], bh[0], bh[1]);
                mma_bf16(acc[mt][2 * p],     ah[mt], bl[0], bl[1]);
                mma_bf16(acc[mt][2 * p],     al[mt], bh[0], bh[1]);
                mma_bf16(acc[mt][2 * p + 1], ah[mt], bh[2], bh[3]);
                mma_bf16(acc[mt][2 * p + 1], ah[mt], bl[2], bl[3]);
                mma_bf16(acc[mt][2 * p + 1], al[mt], bh[2], bh[3]);
            }
        }
    }
}

// ---------------------------------------------------------------------------
// CSR build: zero counts -> count -> scan(3 pass) -> fill
// ---------------------------------------------------------------------------
__global__ void zero_cnt_kernel() {
    int i = blockIdx.x * blockDim.x + threadIdx.x;
    if (i < N_NODES) g_cnt[i] = 0;
}
__global__ void count_kernel(const int* __restrict__ dst) {
    int e = blockIdx.x * blockDim.x + threadIdx.x;
    if (e < N_EDGES) atomicAdd(&g_cnt[dst[e]], 1);
}
__global__ void scan1_kernel() {
    __shared__ int s[256];
    int idx = blockIdx.x * 256 + threadIdx.x;
    int c = (idx < N_NODES) ? g_cnt[idx] : 0;
    s[threadIdx.x] = c;
    __syncthreads();
    // Hillis-Steele inclusive scan
    for (int d = 1; d < 256; d <<= 1) {
        int v = (threadIdx.x >= d) ? s[threadIdx.x - d] : 0;
        __syncthreads();
        s[threadIdx.x] += v;
        __syncthreads();
    }
    if (idx < N_NODES) g_off[idx] = s[threadIdx.x] - c;  // exclusive
    if (threadIdx.x == 255) g_blksum[blockIdx.x] = s[255];
}
__global__ void scan2_kernel() {
    __shared__ int s[256];
    int t = threadIdx.x;
    int v = (t < NBLK_SCAN) ? g_blksum[t] : 0;
    s[t] = v;
    __syncthreads();
    for (int d = 1; d < 256; d <<= 1) {
        int u = (t >= d) ? s[t - d] : 0;
        __syncthreads();
        s[t] += u;
        __syncthreads();
    }
    if (t < NBLK_SCAN) g_blksum[t] = s[t] - v;  // exclusive block offsets
}
__global__ void scan3_kernel() {
    int idx = blockIdx.x * 256 + threadIdx.x;
    if (idx < N_NODES) {
        int o = g_off[idx] + g_blksum[blockIdx.x];
        g_off[idx] = o;
        g_cur[idx] = o;
    }
}
__global__ void fill_kernel(const int* __restrict__ src, const int* __restrict__ dst) {
    int e = blockIdx.x * blockDim.x + threadIdx.x;
    if (e < N_EDGES) {
        int slot = atomicAdd(&g_cur[dst[e]], 1);
        g_eid[slot]  = e;
        g_esrc[slot] = src[e];
    }
}

// ---------------------------------------------------------------------------
// Gather: one warp per node. acc = sum over incoming edges of feat[src]+ef[e].
// No float atomics; h written once (no zero pass needed).
// ---------------------------------------------------------------------------
__global__ void gather_kernel(const float* __restrict__ feat,
                              const float* __restrict__ edge_feat) {
    int node = (blockIdx.x * blockDim.x + threadIdx.x) >> 5;
    int lane = threadIdx.x & 31;
    if (node >= N_NODES) return;
    int beg = g_off[node];
    int cnt = g_cnt[node];

    const float4* f4 = reinterpret_cast<const float4*>(feat);
    const float4* e4 = reinterpret_cast<const float4*>(edge_feat);

    float4 acc0 = make_float4(0.f, 0.f, 0.f, 0.f);
    float4 acc1 = make_float4(0.f, 0.f, 0.f, 0.f);
    int i = 0;
    for (; i + 2 <= cnt; i += 2) {
        int e0 = g_eid[beg + i],     s0 = g_esrc[beg + i];
        int e1 = g_eid[beg + i + 1], s1 = g_esrc[beg + i + 1];
        float4 a0 = f4[(size_t)s0 * 32 + lane];
        float4 b0 = e4[(size_t)e0 * 32 + lane];
        float4 a1 = f4[(size_t)s1 * 32 + lane];
        float4 b1 = e4[(size_t)e1 * 32 + lane];
        acc0.x += a0.x + b0.x; acc0.y += a0.y + b0.y;
        acc0.z += a0.z + b0.z; acc0.w += a0.w + b0.w;
        acc1.x += a1.x + b1.x; acc1.y += a1.y + b1.y;
        acc1.z += a1.z + b1.z; acc1.w += a1.w + b1.w;
    }
    if (i < cnt) {
        int e0 = g_eid[beg + i], s0 = g_esrc[beg + i];
        float4 a0 = f4[(size_t)s0 * 32 + lane];
        float4 b0 = e4[(size_t)e0 * 32 + lane];
        acc0.x += a0.x + b0.x; acc0.y += a0.y + b0.y;
        acc0.z += a0.z + b0.z; acc0.w += a0.w + b0.w;
    }
    float4 r = make_float4(acc0.x + acc1.x, acc0.y + acc1.y,
                           acc0.z + acc1.z, acc0.w + acc1.w);
    reinterpret_cast<float4*>(g_h)[(size_t)node * 32 + lane] = r;
}

// ---------------------------------------------------------------------------
// Weight transpose + split into bf16 hi/lo.
// ---------------------------------------------------------------------------
template <int MODE>
__global__ void wsplit_kernel(const float* __restrict__ W) {
    constexpr int K = (MODE == 1) ? D_IN : D_HID;
    constexpr int N = (MODE == 1) ? D_HID : D_OUT;
    __nv_bfloat16* out_hi = (MODE == 1) ? g_w1t_hi : g_w2t_hi;
    __nv_bfloat16* out_lo = (MODE == 1) ? g_w1t_lo : g_w2t_lo;
    int i = blockIdx.x * blockDim.x + threadIdx.x;
    if (i < K * N) {
        int k = i / N, n = i % N;
        float x = W[i];
        __nv_bfloat16 hi = __float2bfloat16(x);
        out_hi[(size_t)n * K + k] = hi;
        out_lo[(size_t)n * K + k] = __float2bfloat16(x - __bfloat162float(hi));
    }
}

// ---------------------------------------------------------------------------
// FUSED MLP (unchanged from R7). Each CTA: 128 node rows through both layers.
// ---------------------------------------------------------------------------
__global__ __launch_bounds__(256)
void fused_mlp_kernel(const float* __restrict__ b1, const float* __restrict__ b2,
                      float* __restrict__ out) {
    constexpr int OFF_A_HI = 0,       OFF_A_LO = 32768;
    constexpr int OFF_B_HI = 65536,   OFF_B_LO = 98304;
    constexpr int OFF_H_HI = 131072,  OFF_H_LO = 163840;

    extern __shared__ char smem[];
    const uint32_t sb = smem_u32(smem);
    const int tid = threadIdx.x;
    const int lane = tid & 31;
    const int wid  = tid >> 5;
    const int wm   = wid >> 1;
    const int wn   = wid & 1;
    const int row0 = blockIdx.x * 128;

    // ---- load A = h rows, fp32 -> bf16 hi/lo ----
    for (int c = tid; c < 128 * 16; c += 256) {
        int row = c >> 4, ch = c & 15;
        float4 f0 = make_float4(0.f, 0.f, 0.f, 0.f), f1 = f0;
        if (row0 + row < N_NODES) {
            const float* gp = g_h + (size_t)(row0 + row) * D_IN + ch * 8;
            f0 = *reinterpret_cast<const float4*>(gp);
            f1 = *reinterpret_cast<const float4*>(gp + 4);
        }
        uint4 vh, vl;
        vh.x = pack_bf2(f0.x, f0.y); vh.y = pack_bf2(f0.z, f0.w);
        vh.z = pack_bf2(f1.x, f1.y); vh.w = pack_bf2(f1.z, f1.w);
        float r0 = f0.x - __bfloat162float(__float2bfloat16(f0.x));
        float r1 = f0.y - __bfloat162float(__float2bfloat16(f0.y));
        float r2 = f0.z - __bfloat162float(__float2bfloat16(f0.z));
        float r3 = f0.w - __bfloat162float(__float2bfloat16(f0.w));
        float r4 = f1.x - __bfloat162float(__float2bfloat16(f1.x));
        float r5 = f1.y - __bfloat162float(__float2bfloat16(f1.y));
        float r6 = f1.z - __bfloat162float(__float2bfloat16(f1.z));
        float r7 = f1.w - __bfloat162float(__float2bfloat16(f1.w));
        vl.x = pack_bf2(r0, r1); vl.y = pack_bf2(r2, r3);
        vl.z = pack_bf2(r4, r5); vl.w = pack_bf2(r6, r7);
        uint32_t o = toff(row, ch * 16);
        *reinterpret_cast<uint4*>(smem + OFF_A_HI + o) = vh;
        *reinterpret_cast<uint4*>(smem + OFF_A_LO + o) = vl;
    }

    float oacc[2][8][4];
#pragma unroll
    for (int i = 0; i < 2; i++)
#pragma unroll
        for (int j = 0; j < 8; j++)
#pragma unroll
            for (int q = 0; q < 4; q++) oacc[i][j][q] = 0.f;

    for (int c8 = 0; c8 < 8; c8++) {
        for (int c = tid; c < 128 * 16; c += 256) {
            int n = c >> 4, ch = c & 15;
            size_t g = (size_t)(c8 * 128 + n) * D_IN + ch * 8;
            uint4 vh = *reinterpret_cast<const uint4*>(g_w1t_hi + g);
            uint4 vl = *reinterpret_cast<const uint4*>(g_w1t_lo + g);
            uint32_t o = toff(n, ch * 16);
            *reinterpret_cast<uint4*>(smem + OFF_B_HI + o) = vh;
            *reinterpret_cast<uint4*>(smem + OFF_B_LO + o) = vl;
        }
        __syncthreads();

        float hacc[2][8][4];
#pragma unroll
        for (int i = 0; i < 2; i++)
#pragma unroll
            for (int j = 0; j < 8; j++)
#pragma unroll
                for (int q = 0; q < 4; q++) hacc[i][j][q] = 0.f;
        mma_tile_128(sb + OFF_A_HI, sb + OFF_A_LO, sb + OFF_B_HI, sb + OFF_B_LO,
                     hacc, lane, wm, wn);
        __syncthreads();

#pragma unroll
        for (int mt = 0; mt < 2; mt++) {
            int r = wm * 32 + mt * 16 + (lane >> 2);
#pragma unroll
            for (int nt = 0; nt < 8; nt++) {
                int cl = wn * 64 + nt * 8 + (lane & 3) * 2;
                float bv0 = __ldg(b1 + c8 * 128 + cl);
                float bv1 = __ldg(b1 + c8 * 128 + cl + 1);
                float x0 = fmaxf(hacc[mt][nt][0] + bv0, 0.f);
                float x1 = fmaxf(hacc[mt][nt][1] + bv1, 0.f);
                float x2 = fmaxf(hacc[mt][nt][2] + bv0, 0.f);
                float x3 = fmaxf(hacc[mt][nt][3] + bv1, 0.f);
                uint32_t h01 = pack_bf2(x0, x1);
                uint32_t h23 = pack_bf2(x2, x3);
                uint32_t l01 = pack_bf2(x0 - __bfloat162float(__float2bfloat16(x0)),
                                        x1 - __bfloat162float(__float2bfloat16(x1)));
                uint32_t l23 = pack_bf2(x2 - __bfloat162float(__float2bfloat16(x2)),
                                        x3 - __bfloat162float(__float2bfloat16(x3)));
                uint32_t o0 = toff(r,     cl * 2);
                uint32_t o1 = toff(r + 8, cl * 2);
                *reinterpret_cast<uint32_t*>(smem + OFF_H_HI + o0) = h01;
                *reinterpret_cast<uint32_t*>(smem + OFF_H_LO + o0) = l01;
                *reinterpret_cast<uint32_t*>(smem + OFF_H_HI + o1) = h23;
                *reinterpret_cast<uint32_t*>(smem + OFF_H_LO + o1) = l23;
            }
        }

        for (int c = tid; c < 128 * 16; c += 256) {
            int n = c >> 4, ch = c & 15;
            size_t g = (size_t)n * D_HID + c8 * 128 + ch * 8;
            uint4 vh = *reinterpret_cast<const uint4*>(g_w2t_hi + g);
            uint4 vl = *reinterpret_cast<const uint4*>(g_w2t_lo + g);
            uint32_t o = toff(n, ch * 16);
            *reinterpret_cast<uint4*>(smem + OFF_B_HI + o) = vh;
            *reinterpret_cast<uint4*>(smem + OFF_B_LO + o) = vl;
        }
        __syncthreads();

        mma_tile_128(sb + OFF_H_HI, sb + OFF_H_LO, sb + OFF_B_HI, sb + OFF_B_LO,
                     oacc, lane, wm, wn);
        __syncthreads();
    }

#pragma unroll
    for (int mt = 0; mt < 2; mt++) {
        int r = row0 + wm * 32 + mt * 16 + (lane >> 2);
#pragma unroll
        for (int nt = 0; nt < 8; nt++) {
            int col = wn * 64 + nt * 8 + (lane & 3) * 2;
            float bv0 = __ldg(b2 + col), bv1 = __ldg(b2 + col + 1);
            if (r < N_NODES)
                *reinterpret_cast<float2*>(out + (size_t)r * D_OUT + col) =
                    make_float2(oacc[mt][nt][0] + bv0, oacc[mt][nt][1] + bv1);
            if (r + 8 < N_NODES)
                *reinterpret_cast<float2*>(out + (size_t)(r + 8) * D_OUT + col) =
                    make_float2(oacc[mt][nt][2] + bv0, oacc[mt][nt][3] + bv1);
        }
    }
}

// ---------------------------------------------------------------------------
// Launch
// ---------------------------------------------------------------------------
extern "C" void kernel_launch(void* const* d_in, const int* in_sizes, int n_in,
                              void* d_out, int out_size) {
    const float* feat = nullptr; const float* edge_feat = nullptr;
    const int*   src  = nullptr; const int*   dst = nullptr;
    const float* W1   = nullptr; const float* b1  = nullptr;
    const float* W2   = nullptr; const float* b2  = nullptr;

    for (int i = 0; i < n_in; i++) {
        long long sz = in_sizes[i];
        if      (sz == (long long)N_NODES * D_IN)  feat = (const float*)d_in[i];
        else if (sz == (long long)N_EDGES * D_IN)  edge_feat = (const float*)d_in[i];
        else if (sz == (long long)N_EDGES) { if (!src) src = (const int*)d_in[i]; else dst = (const int*)d_in[i]; }
        else if (sz == (long long)D_IN * D_HID) { if (!W1) W1 = (const float*)d_in[i]; else W2 = (const float*)d_in[i]; }
        else if (sz == (long long)D_HID)           b1 = (const float*)d_in[i];
        else if (sz == (long long)D_OUT)           b2 = (const float*)d_in[i];
    }
    float* out = (float*)d_out;

    constexpr int SMEM = 196608;
    cudaFuncSetAttribute(fused_mlp_kernel, cudaFuncAttributeMaxDynamicSharedMemorySize, SMEM);

    // ---- CSR build ----
    zero_cnt_kernel<<<(N_NODES + 255) / 256, 256>>>();
    count_kernel<<<(N_EDGES + 255) / 256, 256>>>(dst);
    scan1_kernel<<<NBLK_SCAN, 256>>>();
    scan2_kernel<<<1, 256>>>();
    scan3_kernel<<<NBLK_SCAN, 256>>>();
    fill_kernel<<<(N_EDGES + 255) / 256, 256>>>(src, dst);

    // ---- gather: h = segment_sum(feat[src] + edge_feat) ----
    { int blocks = (N_NODES * 32 + 255) / 256; gather_kernel<<<blocks, 256>>>(feat, edge_feat); }

    // ---- weight transpose+split ----
    { int n = D_IN * D_HID; wsplit_kernel<1><<<(n + 255) / 256, 256>>>(W1); }
    { int n = D_HID * D_OUT; wsplit_kernel<2><<<(n + 255) / 256, 256>>>(W2); }

    // ---- fused MLP ----
    {
        dim3 grid((N_NODES + 127) / 128);
        fused_mlp_kernel<<<grid, 256, SMEM>>>(b1, b2, out);
    }
}

// round 9
// speedup vs baseline: 1.1030x; 1.1030x over previous
#include <cuda_runtime.h>
#include <cuda_bf16.h>
#include <cstdint>

#define N_NODES 50000
#define N_EDGES 600000
#define D_IN    128
#define D_HID   1024
#define D_OUT   128

// ---------------------------------------------------------------------------
// Device-global scratch. ONLY referenced from device code (host-shadow bug).
// ---------------------------------------------------------------------------
__device__ float         g_h[(size_t)N_NODES * D_IN];
__device__ __nv_bfloat16 g_w1t_hi[(size_t)D_HID * D_IN];      // W1^T [1024][128]
__device__ __nv_bfloat16 g_w1t_lo[(size_t)D_HID * D_IN];
__device__ __nv_bfloat16 g_w2t_hi[(size_t)D_OUT * D_HID];     // W2^T [128][1024]
__device__ __nv_bfloat16 g_w2t_lo[(size_t)D_OUT * D_HID];

// ---------------------------------------------------------------------------
// Helpers
// ---------------------------------------------------------------------------
__device__ __forceinline__ uint32_t smem_u32(const void* p) {
    uint32_t a;
    asm("{ .reg .u64 t; cvta.to.shared.u64 t, %1; cvt.u32.u64 %0, t; }" : "=r"(a) : "l"(p));
    return a;
}
#define SW128(x) ((x) ^ (((x) >> 3) & 0x70))

// 128-row x 128-k tile: two 16KB sub-tiles (k-bytes [0,128),[128,256)), SW128.
__device__ __forceinline__ uint32_t toff(int row, int kbyte) {
    uint32_t w = (uint32_t)(row * 128 + (kbyte & 127));
    return (uint32_t)((kbyte >> 7) * 16384) + SW128(w);
}
// W1 half-tile: 64 rows x 128 k -> two 8KB sub-tiles.
__device__ __forceinline__ uint32_t toffW1(int row, int kbyte) {
    uint32_t w = (uint32_t)(row * 128 + (kbyte & 127));
    return (uint32_t)((kbyte >> 7) * 8192) + SW128(w);
}
// W2 half-tile: 128 rows x 64 k -> one 16KB tile (128B per row).
__device__ __forceinline__ uint32_t toffW2(int row, int kbyte) {
    uint32_t w = (uint32_t)(row * 128 + kbyte);
    return SW128(w);
}

__device__ __forceinline__ void ldsm_x4(uint32_t (&r)[4], uint32_t addr) {
    asm volatile("ldmatrix.sync.aligned.m8n8.x4.shared.b16 {%0,%1,%2,%3}, [%4];"
                 : "=r"(r[0]), "=r"(r[1]), "=r"(r[2]), "=r"(r[3]) : "r"(addr));
}
__device__ __forceinline__ void mma_bf16(float (&d)[4], const uint32_t (&a)[4],
                                         uint32_t b0, uint32_t b1) {
    asm volatile(
        "mma.sync.aligned.m16n8k16.row.col.f32.bf16.bf16.f32 "
        "{%0,%1,%2,%3}, {%4,%5,%6,%7}, {%8,%9}, {%0,%1,%2,%3};"
        : "+f"(d[0]), "+f"(d[1]), "+f"(d[2]), "+f"(d[3])
        : "r"(a[0]), "r"(a[1]), "r"(a[2]), "r"(a[3]), "r"(b0), "r"(b1));
}
__device__ __forceinline__ uint32_t pack_bf2(float x0, float x1) {
    __nv_bfloat162 p = __floats2bfloat162_rn(x0, x1);
    return *reinterpret_cast<uint32_t*>(&p);
}
__device__ __forceinline__ void cp16(uint32_t dst, const void* src) {
    asm volatile("cp.async.cg.shared.global [%0], [%1], 16;" :: "r"(dst), "l"(src));
}

// ---------------------------------------------------------------------------
// Phase 1: zero accumulator
// ---------------------------------------------------------------------------
__global__ void zero_h_kernel() {
    int i = blockIdx.x * blockDim.x + threadIdx.x;
    const int n4 = N_NODES * D_IN / 4;
    if (i < n4) reinterpret_cast<float4*>(g_h)[i] = make_float4(0.f, 0.f, 0.f, 0.f);
}

// ---------------------------------------------------------------------------
// Phase 2: scatter (R7, proven). One warp per edge; float4 atomics.
// ---------------------------------------------------------------------------
__global__ void scatter_kernel(const float* __restrict__ feat,
                               const float* __restrict__ edge_feat,
                               const int*   __restrict__ src,
                               const int*   __restrict__ dst) {
    int warp = (blockIdx.x * blockDim.x + threadIdx.x) >> 5;
    int lane = threadIdx.x & 31;
    if (warp >= N_EDGES) return;
    int s = src[warp], d = dst[warp];
    const float4 a = reinterpret_cast<const float4*>(feat      + (size_t)s    * D_IN)[lane];
    const float4 b = reinterpret_cast<const float4*>(edge_feat + (size_t)warp * D_IN)[lane];
    float4 m = make_float4(a.x + b.x, a.y + b.y, a.z + b.z, a.w + b.w);
    atomicAdd(reinterpret_cast<float4*>(g_h + (size_t)d * D_IN + lane * 4), m);
}

// ---------------------------------------------------------------------------
// Phase 3: merged weight transpose + split (one launch).
// blocks [0,512): W1; blocks [512,1024): W2. 131072 elems each.
// ---------------------------------------------------------------------------
__global__ void wsplit_kernel(const float* __restrict__ W1, const float* __restrict__ W2) {
    int b = blockIdx.x;
    if (b < 512) {
        int i = b * 256 + threadIdx.x;               // over W1 [128][1024]
        int k = i >> 10, n = i & 1023;
        float x = W1[i];
        __nv_bfloat16 hi = __float2bfloat16(x);
        g_w1t_hi[(size_t)n * D_IN + k] = hi;
        g_w1t_lo[(size_t)n * D_IN + k] = __float2bfloat16(x - __bfloat162float(hi));
    } else {
        int i = (b - 512) * 256 + threadIdx.x;       // over W2 [1024][128]
        int k = i >> 7, n = i & 127;
        float x = W2[i];
        __nv_bfloat16 hi = __float2bfloat16(x);
        g_w2t_hi[(size_t)n * D_HID + k] = hi;
        g_w2t_lo[(size_t)n * D_HID + k] = __float2bfloat16(x - __bfloat162float(hi));
    }
}

// ---------------------------------------------------------------------------
// Phase 4: cp.async-pipelined fused MLP.
// Smem: A(64K) + H(64K) + 3x32K weight ring = 224KB, 1 CTA/SM.
// Tiles per chunk: W1h0, W1h1 (64n x 128k), W2k0, W2k1 (128n x 64k); prefetch 2.
// ---------------------------------------------------------------------------
#define OFF_A_HI 0
#define OFF_A_LO 32768
#define OFF_H_HI 65536
#define OFF_H_LO 98304
#define OFF_WB   131072      // 3 buffers x 32KB (hi 16K + lo 16K)

__device__ __forceinline__ void load_tile(char* smem, int t, int wq) {
    const int c8 = t >> 2, j = t & 3;
    const int tid = threadIdx.x;
    const uint32_t base = smem_u32(smem) + OFF_WB + wq * 32768;
    if (j < 2) {           // W1 half j: rows c8*128 + j*64 + [0,64), k [0,128)
#pragma unroll
        for (int c = tid; c < 64 * 16; c += 256) {
            int row = c >> 4, ch = c & 15;
            size_t g = (size_t)(c8 * 128 + j * 64 + row) * D_IN + ch * 8;
            uint32_t o = toffW1(row, ch * 16);
            cp16(base + o,         g_w1t_hi + g);
            cp16(base + 16384 + o, g_w1t_lo + g);
        }
    } else {               // W2 half (j-2): rows [0,128), k c8*128 + (j-2)*64 + [0,64)
        const int kh = j - 2;
#pragma unroll
        for (int c = tid; c < 128 * 8; c += 256) {
            int row = c >> 3, ch = c & 7;
            size_t g = (size_t)row * D_HID + c8 * 128 + kh * 64 + ch * 8;
            uint32_t o = toffW2(row, ch * 16);
            cp16(base + o,         g_w2t_hi + g);
            cp16(base + 16384 + o, g_w2t_lo + g);
        }
    }
    asm volatile("cp.async.commit_group;" ::: "memory");
}

__global__ __launch_bounds__(256)
void fused_mlp_kernel(const float* __restrict__ b1, const float* __restrict__ b2,
                      float* __restrict__ out) {
    extern __shared__ char smem[];
    const uint32_t sb = smem_u32(smem);
    const int tid = threadIdx.x;
    const int lane = tid & 31;
    const int wid  = tid >> 5;
    const int wm   = wid >> 1;
    const int wn   = wid & 1;
    const int row0 = blockIdx.x * 128;

    // prologue: start first two weight tiles before A conversion
    load_tile(smem, 0, 0);
    load_tile(smem, 1, 1);

    // ---- load A = h rows, fp32 -> bf16 hi/lo (plain stores) ----
    for (int c = tid; c < 128 * 16; c += 256) {
        int row = c >> 4, ch = c & 15;
        float4 f0 = make_float4(0.f, 0.f, 0.f, 0.f), f1 = f0;
        if (row0 + row < N_NODES) {
            const float* gp = g_h + (size_t)(row0 + row) * D_IN + ch * 8;
            f0 = *reinterpret_cast<const float4*>(gp);
            f1 = *reinterpret_cast<const float4*>(gp + 4);
        }
        uint4 vh, vl;
        vh.x = pack_bf2(f0.x, f0.y); vh.y = pack_bf2(f0.z, f0.w);
        vh.z = pack_bf2(f1.x, f1.y); vh.w = pack_bf2(f1.z, f1.w);
        vl.x = pack_bf2(f0.x - __bfloat162float(__float2bfloat16(f0.x)),
                        f0.y - __bfloat162float(__float2bfloat16(f0.y)));
        vl.y = pack_bf2(f0.z - __bfloat162float(__float2bfloat16(f0.z)),
                        f0.w - __bfloat162float(__float2bfloat16(f0.w)));
        vl.z = pack_bf2(f1.x - __bfloat162float(__float2bfloat16(f1.x)),
                        f1.y - __bfloat162float(__float2bfloat16(f1.y)));
        vl.w = pack_bf2(f1.z - __bfloat162float(__float2bfloat16(f1.z)),
                        f1.w - __bfloat162float(__float2bfloat16(f1.w)));
        uint32_t o = toff(row, ch * 16);
        *reinterpret_cast<uint4*>(smem + OFF_A_HI + o) = vh;
        *reinterpret_cast<uint4*>(smem + OFF_A_LO + o) = vl;
    }

    float oacc[2][8][4];
#pragma unroll
    for (int i = 0; i < 2; i++)
#pragma unroll
        for (int j = 0; j < 8; j++)
#pragma unroll
            for (int q = 0; q < 4; q++) oacc[i][j][q] = 0.f;

    for (int c8 = 0; c8 < 8; c8++) {
        float hacc[2][8][4];
#pragma unroll
        for (int i = 0; i < 2; i++)
#pragma unroll
            for (int j = 0; j < 8; j++)
#pragma unroll
                for (int q = 0; q < 4; q++) hacc[i][j][q] = 0.f;

#pragma unroll
        for (int j = 0; j < 4; j++) {
            const int t = c8 * 4 + j;
            // tile t must be resident; tile t+1 may still be in flight
            if (t == 31) asm volatile("cp.async.wait_group 0;" ::: "memory");
            else         asm volatile("cp.async.wait_group 1;" ::: "memory");
            __syncthreads();   // also: all warps done with tile t-1 (ring reuse safe)
            if (t + 2 < 32) load_tile(smem, t + 2, (t + 2) % 3);

            const uint32_t wb_hi = sb + OFF_WB + (t % 3) * 32768;
            const uint32_t wb_lo = wb_hi + 16384;

            if (j < 2) {
                // ---- stage 1 half j: hacc[nt = j*4 + p*2 + {0,1}] ----
#pragma unroll
                for (int ks = 0; ks < 8; ks++) {
                    const int kb = ks * 32;
                    uint32_t ah[2][4], al[2][4];
#pragma unroll
                    for (int mt = 0; mt < 2; mt++) {
                        int arow = wm * 32 + mt * 16 + (lane & 15);
                        uint32_t off = toff(arow, kb + (lane >> 4) * 16);
                        ldsm_x4(ah[mt], sb + OFF_A_HI + off);
                        ldsm_x4(al[mt], sb + OFF_A_LO + off);
                    }
#pragma unroll
                    for (int p = 0; p < 2; p++) {
                        int brow = wn * 32 + p * 16 + (lane >> 4) * 8 + (lane & 7);
                        uint32_t off = toffW1(brow, kb + ((lane >> 3) & 1) * 16);
                        uint32_t bh[4], bl[4];
                        ldsm_x4(bh, wb_hi + off);
                        ldsm_x4(bl, wb_lo + off);
                        const int nt0 = j * 4 + p * 2;
#pragma unroll
                        for (int mt = 0; mt < 2; mt++) {
                            mma_bf16(hacc[mt][nt0],     ah[mt], bh[0], bh[1]);
                            mma_bf16(hacc[mt][nt0],     ah[mt], bl[0], bl[1]);
                            mma_bf16(hacc[mt][nt0],     al[mt], bh[0], bh[1]);
                            mma_bf16(hacc[mt][nt0 + 1], ah[mt], bh[2], bh[3]);
                            mma_bf16(hacc[mt][nt0 + 1], ah[mt], bl[2], bl[3]);
                            mma_bf16(hacc[mt][nt0 + 1], al[mt], bh[2], bh[3]);
                        }
                    }
                }
                if (j == 1) {
                    // ---- bias + relu + split -> H ----
#pragma unroll
                    for (int mt = 0; mt < 2; mt++) {
                        int r = wm * 32 + mt * 16 + (lane >> 2);
#pragma unroll
                        for (int nt = 0; nt < 8; nt++) {
                            int hh = nt >> 2, ntl = nt & 3;
                            int cl = hh * 64 + wn * 32 + ntl * 8 + (lane & 3) * 2;
                            float bv0 = __ldg(b1 + c8 * 128 + cl);
                            float bv1 = __ldg(b1 + c8 * 128 + cl + 1);
                            float x0 = fmaxf(hacc[mt][nt][0] + bv0, 0.f);
                            float x1 = fmaxf(hacc[mt][nt][1] + bv1, 0.f);
                            float x2 = fmaxf(hacc[mt][nt][2] + bv0, 0.f);
                            float x3 = fmaxf(hacc[mt][nt][3] + bv1, 0.f);
                            uint32_t o0 = toff(r,     cl * 2);
                            uint32_t o1 = toff(r + 8, cl * 2);
                            *reinterpret_cast<uint32_t*>(smem + OFF_H_HI + o0) = pack_bf2(x0, x1);
                            *reinterpret_cast<uint32_t*>(smem + OFF_H_LO + o0) =
                                pack_bf2(x0 - __bfloat162float(__float2bfloat16(x0)),
                                         x1 - __bfloat162float(__float2bfloat16(x1)));
                            *reinterpret_cast<uint32_t*>(smem + OFF_H_HI + o1) = pack_bf2(x2, x3);
                            *reinterpret_cast<uint32_t*>(smem + OFF_H_LO + o1) =
                                pack_bf2(x2 - __bfloat162float(__float2bfloat16(x2)),
                                         x3 - __bfloat162float(__float2bfloat16(x3)));
                        }
                    }
                }
            } else {
                // ---- stage 2 k-half (j-2): oacc += H[:, kh] @ W2[kh] ----
                const int kh = j - 2;
#pragma unroll
                for (int ks = 0; ks < 4; ks++) {
                    const int kbH = kh * 128 + ks * 32;
                    const int kbW = ks * 32;
                    uint32_t ah[2][4], al[2][4];
#pragma unroll
                    for (int mt = 0; mt < 2; mt++) {
                        int arow = wm * 32 + mt * 16 + (lane & 15);
                        uint32_t off = toff(arow, kbH + (lane >> 4) * 16);
                        ldsm_x4(ah[mt], sb + OFF_H_HI + off);
                        ldsm_x4(al[mt], sb + OFF_H_LO + off);
                    }
#pragma unroll
                    for (int p = 0; p < 4; p++) {
                        int brow = wn * 64 + p * 16 + (lane >> 4) * 8 + (lane & 7);
                        uint32_t off = toffW2(brow, kbW + ((lane >> 3) & 1) * 16);
                        uint32_t bh[4], bl[4];
                        ldsm_x4(bh, wb_hi + off);
                        ldsm_x4(bl, wb_lo + off);
#pragma unroll
                        for (int mt = 0; mt < 2; mt++) {
                            mma_bf16(oacc[mt][2 * p],     ah[mt], bh[0], bh[1]);
                            mma_bf16(oacc[mt][2 * p],     ah[mt], bl[0], bl[1]);
                            mma_bf16(oacc[mt][2 * p],     al[mt], bh[0], bh[1]);
                            mma_bf16(oacc[mt][2 * p + 1], ah[mt], bh[2], bh[3]);
                            mma_bf16(oacc[mt][2 * p + 1], ah[mt], bl[2], bl[3]);
                            mma_bf16(oacc[mt][2 * p + 1], al[mt], bh[2], bh[3]);
                        }
                    }
                }
            }
        }
    }

    // ---- final epilogue: out = oacc + b2 ----
#pragma unroll
    for (int mt = 0; mt < 2; mt++) {
        int r = row0 + wm * 32 + mt * 16 + (lane >> 2);
#pragma unroll
        for (int nt = 0; nt < 8; nt++) {
            int col = wn * 64 + nt * 8 + (lane & 3) * 2;
            float bv0 = __ldg(b2 + col), bv1 = __ldg(b2 + col + 1);
            if (r < N_NODES)
                *reinterpret_cast<float2*>(out + (size_t)r * D_OUT + col) =
                    make_float2(oacc[mt][nt][0] + bv0, oacc[mt][nt][1] + bv1);
            if (r + 8 < N_NODES)
                *reinterpret_cast<float2*>(out + (size_t)(r + 8) * D_OUT + col) =
                    make_float2(oacc[mt][nt][2] + bv0, oacc[mt][nt][3] + bv1);
        }
    }
}

// ---------------------------------------------------------------------------
// Launch: zero(0), scatter(1), wsplit(2), fusedMLP(3)  [index 3 gets profiled]
// ---------------------------------------------------------------------------
extern "C" void kernel_launch(void* const* d_in, const int* in_sizes, int n_in,
                              void* d_out, int out_size) {
    const float* feat = nullptr; const float* edge_feat = nullptr;
    const int*   src  = nullptr; const int*   dst = nullptr;
    const float* W1   = nullptr; const float* b1  = nullptr;
    const float* W2   = nullptr; const float* b2  = nullptr;

    for (int i = 0; i < n_in; i++) {
        long long sz = in_sizes[i];
        if      (sz == (long long)N_NODES * D_IN)  feat = (const float*)d_in[i];
        else if (sz == (long long)N_EDGES * D_IN)  edge_feat = (const float*)d_in[i];
        else if (sz == (long long)N_EDGES) { if (!src) src = (const int*)d_in[i]; else dst = (const int*)d_in[i]; }
        else if (sz == (long long)D_IN * D_HID) { if (!W1) W1 = (const float*)d_in[i]; else W2 = (const float*)d_in[i]; }
        else if (sz == (long long)D_HID)           b1 = (const float*)d_in[i];
        else if (sz == (long long)D_OUT)           b2 = (const float*)d_in[i];
    }
    float* out = (float*)d_out;

    constexpr int SMEM = 131072 + 3 * 32768;   // 229376 B = 224KB
    cudaFuncSetAttribute(fused_mlp_kernel, cudaFuncAttributeMaxDynamicSharedMemorySize, SMEM);

    { int n4 = N_NODES * D_IN / 4; zero_h_kernel<<<(n4 + 255) / 256, 256>>>(); }
    { int blocks = (N_EDGES + 7) / 8; scatter_kernel<<<blocks, 256>>>(feat, edge_feat, src, dst); }
    wsplit_kernel<<<1024, 256>>>(W1, W2);
    {
        dim3 grid((N_NODES + 127) / 128);
        fused_mlp_kernel<<<grid, 256, SMEM>>>(b1, b2, out);
    }
}